// round 17
// baseline (speedup 1.0000x reference)
#include <cuda_runtime.h>
#include <cstdint>

#define N_NODES 100000
#define N_EDGES 640000
#define HID     128

typedef unsigned long long ull;

// ---------------- scratch (static device globals; no allocation) ----------------
__device__ float  g_A[(size_t)N_NODES * HID];   // embed out / T2
__device__ float  g_B[(size_t)N_NODES * HID];   // T1
__device__ float  g_S[(size_t)N_NODES * HID];   // Y = X * W^3
__device__ int    g_cnt[N_NODES];
__device__ int    g_rowptr[N_NODES];
__device__ int    g_cursor[N_NODES];
__device__ ull    g_csr_pack[N_EDGES];          // {val:32 | src:32} packed edges
__device__ int    g_blocksums[128];
__device__ double g_W2d[128 * 128];             // W^2 in fp64
__device__ float  g_W3[128 * 128];              // W^3 fp32 (GEMM operand)
__device__ float  g_c1[HID];                    // b^T W
__device__ float  g_c2[HID];                    // b^T W^2
__device__ float  g_deg1[N_NODES];              // A·1
__device__ float  g_deg2[N_NODES];              // A²·1

// ---------------- small matrix prep (fp64 accumulation) ----------------
__global__ void w2_kernel(const float* __restrict__ W) {
    int i = blockIdx.x * blockDim.x + threadIdx.x;   // 16384
    int r = i >> 7, c = i & 127;
    double acc = 0.0;
    for (int k = 0; k < 128; k++)
        acc += (double)W[r * 128 + k] * (double)W[k * 128 + c];
    g_W2d[i] = acc;
}

__global__ void w3_kernel(const float* __restrict__ W) {
    int i = blockIdx.x * blockDim.x + threadIdx.x;
    int r = i >> 7, c = i & 127;
    double acc = 0.0;
    for (int k = 0; k < 128; k++)
        acc += g_W2d[r * 128 + k] * (double)W[k * 128 + c];
    g_W3[i] = (float)acc;
}

__global__ void c12_kernel(const float* __restrict__ W, const float* __restrict__ b) {
    int j = threadIdx.x;   // 128
    double a1 = 0.0, a2 = 0.0;
    for (int k = 0; k < 128; k++) {
        double bk = (double)b[k];
        a1 += bk * (double)W[k * 128 + j];
        a2 += bk * g_W2d[k * 128 + j];
    }
    g_c1[j] = (float)a1;
    g_c2[j] = (float)a2;
}

// ---------------- CSR build ----------------
__global__ void hist_kernel(const int* __restrict__ dst) {
    int e = blockIdx.x * blockDim.x + threadIdx.x;
    if (e < N_EDGES) atomicAdd(&g_cnt[dst[e]], 1);
}

__global__ void scan1_kernel() {
    __shared__ int sh[1024];
    int tid = threadIdx.x;
    int i = blockIdx.x * 1024 + tid;
    int v = (i < N_NODES) ? g_cnt[i] : 0;
    sh[tid] = v;
    __syncthreads();
    for (int off = 1; off < 1024; off <<= 1) {
        int t = (tid >= off) ? sh[tid - off] : 0;
        __syncthreads();
        sh[tid] += t;
        __syncthreads();
    }
    if (i < N_NODES) g_rowptr[i] = sh[tid] - v;   // exclusive
    if (tid == 1023) g_blocksums[blockIdx.x] = sh[1023];
}

__global__ void scan2_kernel(int nblocks) {
    __shared__ int sh[128];
    int tid = threadIdx.x;
    int v = (tid < nblocks) ? g_blocksums[tid] : 0;
    sh[tid] = v;
    __syncthreads();
    for (int off = 1; off < 128; off <<= 1) {
        int t = (tid >= off) ? sh[tid - off] : 0;
        __syncthreads();
        sh[tid] += t;
        __syncthreads();
    }
    if (tid < nblocks) g_blocksums[tid] = sh[tid] - v;   // exclusive
}

__global__ void scan3_kernel() {
    int i = blockIdx.x * 1024 + threadIdx.x;
    if (i < N_NODES) {
        int r = g_rowptr[i] + g_blocksums[blockIdx.x];
        g_rowptr[i] = r;
        g_cursor[i] = r;
    }
}

__global__ void scatter_kernel(const int* __restrict__ src,
                               const int* __restrict__ dst,
                               const float* __restrict__ val) {
    int e = blockIdx.x * blockDim.x + threadIdx.x;
    if (e < N_EDGES) {
        int d = dst[e];
        int pos = atomicAdd(&g_cursor[d], 1);
        ull p = (ull)(unsigned)src[e] | ((ull)__float_as_uint(val[e]) << 32);
        g_csr_pack[pos] = p;
    }
}

// ---------------- degree vectors: deg1 = A·1, deg2 = A·deg1 ----------------
__global__ void deg1_kernel() {
    int i = blockIdx.x * blockDim.x + threadIdx.x;
    if (i >= N_NODES) return;
    int s = g_rowptr[i], e = g_cursor[i];
    float acc = 0.f;
    for (int j = s; j < e; j++)
        acc += __uint_as_float((unsigned)(g_csr_pack[j] >> 32));
    g_deg1[i] = acc;
}

__global__ void deg2_kernel() {
    int i = blockIdx.x * blockDim.x + threadIdx.x;
    if (i >= N_NODES) return;
    int s = g_rowptr[i], e = g_cursor[i];
    float acc = 0.f;
    for (int j = s; j < e; j++) {
        ull p = g_csr_pack[j];
        acc += __uint_as_float((unsigned)(p >> 32)) * g_deg1[(unsigned)(p & 0xffffffffu)];
    }
    g_deg2[i] = acc;
}

// ---------------- embedding concat ----------------
__global__ void embed_kernel(const int* __restrict__ nodef,
                             const int* __restrict__ typef,
                             const int* __restrict__ lenf,
                             const int* __restrict__ lanef,
                             const float* __restrict__ node_emb,
                             const float* __restrict__ type_emb,
                             const float* __restrict__ len_emb,
                             const float* __restrict__ lane_emb) {
    int u = blockIdx.x * blockDim.x + threadIdx.x;
    if (u >= N_NODES * 32) return;
    int n = u >> 5;
    int c = u & 31;
    float4 v;
    if (c < 4) {
        int f = lanef[n];
        v = reinterpret_cast<const float4*>(lane_emb + (size_t)f * 16)[c];
    } else if (c < 12) {
        int f = typef[n];
        v = reinterpret_cast<const float4*>(type_emb + (size_t)f * 32)[c - 4];
    } else if (c < 16) {
        int f = lenf[n];
        v = reinterpret_cast<const float4*>(len_emb + (size_t)f * 16)[c - 12];
    } else {
        int f = nodef[n];
        v = reinterpret_cast<const float4*>(node_emb + (size_t)f * 64)[c - 16];
    }
    reinterpret_cast<float4*>(g_A)[u] = v;
}

// ---------------- GEMM: FFMA2, LDS.128 dual-k2, 4-way col split ----------------
// S[r][c] = sum_k X[r][k] * W[k][c].  Runs ONCE with W = W^3.
// Grid 296 persistent CTAs = 4 col-quarters x 74; quarter q = blockIdx.x & 3 owns
// cols [q*32, q*32+32); CTA strides row-tiles of 128 rows by 74.
// W quarter repacked k2-major: wq[c][k2] = {W[2k2][c], W[2k2+1][c]}, stride 66 ull
// (528B: 16B-aligned, +4 banks per c -> conflict-free LDS.128 across 8 tx lanes).
// X tile natural (128 x 132 floats); thread rows rq+32i (rq=tid>>3, +4 banks/lane).
// Inner loop per 2 k2: 4 W LDS.128 + 4 X LDS.128 (8 wavefronts) + 32 FFMA2
// (16 fma SM-cyc x 16 warps) -> crossbar at 50%, fma-bound.
#define XN_STRIDE 132
#define WQ_STRIDE 66
#define ROW_TILES ((N_NODES + 127) / 128)     // 782
#define SMEM_GEMM (32 * WQ_STRIDE * 8 + 128 * XN_STRIDE * 4)   // 16896+67584=84480

__device__ __forceinline__ void ffma2(ull& acc, ull a, ull b) {
    asm("fma.rn.f32x2 %0, %1, %2, %0;" : "+l"(acc) : "l"(a), "l"(b));
}

__global__ __launch_bounds__(256, 2)
void gemm_kernel(const float* __restrict__ X,
                 const float* __restrict__ W,
                 float* __restrict__ S) {
    extern __shared__ float sh[];
    ull*   wq = reinterpret_cast<ull*>(sh);                    // [32 c][66 k2-slots]
    float* xs = sh + 32 * WQ_STRIDE * 2;                       // 128 x XN_STRIDE
    int tid = threadIdx.x;
    int q = blockIdx.x & 3;
    int cbase = q * 32;

    // pack W quarter, k2-major: wq[c*66 + k2] = {W[2k2][cbase+c], W[2k2+1][cbase+c]}
    for (int i = tid; i < 32 * 64; i += 256) {
        int c = i >> 6, k2 = i & 63;
        float w0 = W[(2 * k2) * 128 + cbase + c];
        float w1 = W[(2 * k2 + 1) * 128 + cbase + c];
        ull v;
        asm("mov.b64 %0, {%1, %2};" : "=l"(v) : "f"(w0), "f"(w1));
        wq[c * WQ_STRIDE + k2] = v;
    }

    int tx = tid & 7;          // col lane (8)
    int rq = tid >> 3;         // row lane (32)

    for (int tile = blockIdx.x >> 2; tile < ROW_TILES; tile += 74) {
        int row0 = tile * 128;
        __syncthreads();   // previous iter readers done with xs (wq ready iter 0)
        // fill X tile (natural float4; 132*4=528=33*16 aligned)
        for (int i = tid; i < 128 * 32; i += 256) {
            int r = i >> 5, c4 = i & 31;
            int gr = row0 + r;
            float4 v = make_float4(0.f, 0.f, 0.f, 0.f);
            if (gr < N_NODES)
                v = reinterpret_cast<const float4*>(X + (size_t)gr * 128)[c4];
            *reinterpret_cast<float4*>(xs + r * XN_STRIDE + 4 * c4) = v;
        }
        __syncthreads();

        ull acc[4][4];
#pragma unroll
        for (int i = 0; i < 4; i++)
#pragma unroll
            for (int j = 0; j < 4; j++) acc[i][j] = 0ull;

#pragma unroll 4
        for (int k2 = 0; k2 < 64; k2 += 2) {
            ulonglong2 w[4];
#pragma unroll
            for (int j = 0; j < 4; j++)
                w[j] = *reinterpret_cast<const ulonglong2*>(&wq[(tx + 8 * j) * WQ_STRIDE + k2]);
            ulonglong2 x[4];
#pragma unroll
            for (int i = 0; i < 4; i++)
                x[i] = *reinterpret_cast<const ulonglong2*>(xs + (rq + 32 * i) * XN_STRIDE + 2 * k2);
#pragma unroll
            for (int i = 0; i < 4; i++)
#pragma unroll
                for (int j = 0; j < 4; j++) {
                    ffma2(acc[i][j], x[i].x, w[j].x);   // k2
                    ffma2(acc[i][j], x[i].y, w[j].y);   // k2+1
                }
        }

        // epilogue: combine even/odd partial sums, store
#pragma unroll
        for (int i = 0; i < 4; i++) {
            int gr = row0 + rq + 32 * i;
            if (gr < N_NODES) {
                float* out = S + (size_t)gr * 128 + cbase + tx;
#pragma unroll
                for (int j = 0; j < 4; j++) {
                    float2 a = *reinterpret_cast<float2*>(&acc[i][j]);
                    out[8 * j] = a.x + a.y;
                }
            }
        }
    }
}

// ---------------- aggregation (MLP-4 unrolled, packed edges) ----------------
__device__ __forceinline__ void agg_body(const float* __restrict__ S,
                                         float* __restrict__ out,
                                         int node, int lane, float4 acc) {
    int s = g_rowptr[node];
    int e = g_cursor[node];
    int j = s;
    for (; j + 4 <= e; j += 4) {
        ull p0 = __ldg(&g_csr_pack[j]);
        ull p1 = __ldg(&g_csr_pack[j + 1]);
        ull p2 = __ldg(&g_csr_pack[j + 2]);
        ull p3 = __ldg(&g_csr_pack[j + 3]);
        const float4* r0 = reinterpret_cast<const float4*>(S + (size_t)(unsigned)(p0 & 0xffffffffu) * 128);
        const float4* r1 = reinterpret_cast<const float4*>(S + (size_t)(unsigned)(p1 & 0xffffffffu) * 128);
        const float4* r2 = reinterpret_cast<const float4*>(S + (size_t)(unsigned)(p2 & 0xffffffffu) * 128);
        const float4* r3 = reinterpret_cast<const float4*>(S + (size_t)(unsigned)(p3 & 0xffffffffu) * 128);
        float4 x0 = __ldg(&r0[lane]);
        float4 x1 = __ldg(&r1[lane]);
        float4 x2 = __ldg(&r2[lane]);
        float4 x3 = __ldg(&r3[lane]);
        float v0 = __uint_as_float((unsigned)(p0 >> 32));
        float v1 = __uint_as_float((unsigned)(p1 >> 32));
        float v2 = __uint_as_float((unsigned)(p2 >> 32));
        float v3 = __uint_as_float((unsigned)(p3 >> 32));
        acc.x = fmaf(v0, x0.x, acc.x); acc.y = fmaf(v0, x0.y, acc.y);
        acc.z = fmaf(v0, x0.z, acc.z); acc.w = fmaf(v0, x0.w, acc.w);
        acc.x = fmaf(v1, x1.x, acc.x); acc.y = fmaf(v1, x1.y, acc.y);
        acc.z = fmaf(v1, x1.z, acc.z); acc.w = fmaf(v1, x1.w, acc.w);
        acc.x = fmaf(v2, x2.x, acc.x); acc.y = fmaf(v2, x2.y, acc.y);
        acc.z = fmaf(v2, x2.z, acc.z); acc.w = fmaf(v2, x2.w, acc.w);
        acc.x = fmaf(v3, x3.x, acc.x); acc.y = fmaf(v3, x3.y, acc.y);
        acc.z = fmaf(v3, x3.z, acc.z); acc.w = fmaf(v3, x3.w, acc.w);
    }
    for (; j < e; j++) {
        ull p = __ldg(&g_csr_pack[j]);
        float v = __uint_as_float((unsigned)(p >> 32));
        const float4* r = reinterpret_cast<const float4*>(S + (size_t)(unsigned)(p & 0xffffffffu) * 128);
        float4 x = __ldg(&r[lane]);
        acc.x = fmaf(v, x.x, acc.x); acc.y = fmaf(v, x.y, acc.y);
        acc.z = fmaf(v, x.z, acc.z); acc.w = fmaf(v, x.w, acc.w);
    }
    reinterpret_cast<float4*>(out + (size_t)node * 128)[lane] = acc;
}

__global__ void agg_plain_kernel(const float* __restrict__ S,
                                 float* __restrict__ out) {
    int warp = (blockIdx.x * blockDim.x + threadIdx.x) >> 5;
    int lane = threadIdx.x & 31;
    if (warp >= N_NODES) return;
    agg_body(S, out, warp, lane, make_float4(0.f, 0.f, 0.f, 0.f));
}

// out[d] = A·T2 [d] + deg2[d]*c2 + deg1[d]*c1 + b
__global__ void agg_final_kernel(const float* __restrict__ S,
                                 const float* __restrict__ b,
                                 float* __restrict__ out) {
    int warp = (blockIdx.x * blockDim.x + threadIdx.x) >> 5;
    int lane = threadIdx.x & 31;
    if (warp >= N_NODES) return;
    float d1 = g_deg1[warp], d2 = g_deg2[warp];
    float4 bv  = reinterpret_cast<const float4*>(b)[lane];
    float4 c1v = reinterpret_cast<const float4*>(g_c1)[lane];
    float4 c2v = reinterpret_cast<const float4*>(g_c2)[lane];
    float4 acc;
    acc.x = bv.x + d1 * c1v.x + d2 * c2v.x;
    acc.y = bv.y + d1 * c1v.y + d2 * c2v.y;
    acc.z = bv.z + d1 * c1v.z + d2 * c2v.z;
    acc.w = bv.w + d1 * c1v.w + d2 * c2v.w;
    agg_body(S, out, warp, lane, acc);
}

// ---------------- launch ----------------
extern "C" void kernel_launch(void* const* d_in, const int* in_sizes, int n_in,
                              void* d_out, int out_size) {
    const int*   nodef    = (const int*)d_in[0];
    const int*   typef    = (const int*)d_in[1];
    const int*   lenf     = (const int*)d_in[2];
    const int*   lanef    = (const int*)d_in[3];
    const int*   adj_src  = (const int*)d_in[4];
    const int*   adj_dst  = (const int*)d_in[5];
    const float* adj_val  = (const float*)d_in[6];
    const float* node_emb = (const float*)d_in[7];
    const float* type_emb = (const float*)d_in[8];
    const float* len_emb  = (const float*)d_in[9];
    const float* lane_emb = (const float*)d_in[10];
    const float* W        = (const float*)d_in[11];
    const float* b        = (const float*)d_in[12];
    float* out = (float*)d_out;

    float *pA, *pB, *pS, *pW3;
    int* pcnt;
    cudaGetSymbolAddress((void**)&pA, g_A);
    cudaGetSymbolAddress((void**)&pB, g_B);
    cudaGetSymbolAddress((void**)&pS, g_S);
    cudaGetSymbolAddress((void**)&pW3, g_W3);
    cudaGetSymbolAddress((void**)&pcnt, g_cnt);

    cudaFuncSetAttribute(gemm_kernel, cudaFuncAttributeMaxDynamicSharedMemorySize, SMEM_GEMM);

    const int gemm_blocks = 296;                        // 4 quarters x 74, 2 CTAs/SM
    const int agg_blocks  = (N_NODES * 32 + 255) / 256;
    const int nscan = (N_NODES + 1023) / 1024;          // 98

    // idx 0..4 ordered so ncu (launch index 4) captures the GEMM:
    cudaMemsetAsync(pcnt, 0, N_NODES * sizeof(int));                            // 0
    embed_kernel<<<(N_NODES * 32 + 255) / 256, 256>>>(nodef, typef, lenf, lanef,
                                                      node_emb, type_emb, len_emb, lane_emb); // 1
    w2_kernel<<<64, 256>>>(W);                                                  // 2
    w3_kernel<<<64, 256>>>(W);                                                  // 3
    gemm_kernel<<<gemm_blocks, 256, SMEM_GEMM>>>(pA, pW3, pS);                  // 4 (profiled)
    c12_kernel<<<1, 128>>>(W, b);                                               // 5
    hist_kernel<<<(N_EDGES + 255) / 256, 256>>>(adj_dst);                       // 6
    scan1_kernel<<<nscan, 1024>>>();                                            // 7
    scan2_kernel<<<1, 128>>>(nscan);                                            // 8
    scan3_kernel<<<nscan, 1024>>>();                                            // 9
    scatter_kernel<<<(N_EDGES + 255) / 256, 256>>>(adj_src, adj_dst, adj_val);  // 10
    deg1_kernel<<<(N_NODES + 255) / 256, 256>>>();                              // 11
    deg2_kernel<<<(N_NODES + 255) / 256, 256>>>();                              // 12

    // A^3 applied to Y, rank-1 bias corrections in the last pass
    agg_plain_kernel<<<agg_blocks, 256>>>(pS, pB);        // T1 = A·Y
    agg_plain_kernel<<<agg_blocks, 256>>>(pB, pA);        // T2 = A·T1
    agg_final_kernel<<<agg_blocks, 256>>>(pA, b, out);    // out = A·T2 + corrections
}